// round 1
// baseline (speedup 1.0000x reference)
#include <cuda_runtime.h>
#include <cuda_bf16.h>
#include <cstdint>

// Inputs (metadata order matches setup_inputs dict):
//   d_in[0] = x      float32 [262144]
//   d_in[1] = A_vals float32 [NNZ]
//   d_in[2] = A_rows int32   [NNZ]
//   d_in[3] = A_cols int32   [NNZ]
// Output: float32 [262144]

__global__ void zero_out_kernel(float4* __restrict__ out, int n4) {
    int i = blockIdx.x * blockDim.x + threadIdx.x;
    if (i < n4) out[i] = make_float4(0.f, 0.f, 0.f, 0.f);
}

__global__ void __launch_bounds__(256) coo_spmv_kernel(
    const float* __restrict__ x,
    const float4* __restrict__ vals4,
    const int4* __restrict__ rows4,
    const int4* __restrict__ cols4,
    float* __restrict__ out,
    int nnz4)
{
    int i = blockIdx.x * blockDim.x + threadIdx.x;
    if (i >= nnz4) return;

    // Three independent 16B streaming loads -> MLP 3 per thread
    float4 v = __ldg(&vals4[i]);
    int4   r = __ldg(&rows4[i]);
    int4   c = __ldg(&cols4[i]);

    // x gather: L2-resident (x is 1 MB)
    float x0 = __ldg(&x[c.x]);
    float x1 = __ldg(&x[c.y]);
    float x2 = __ldg(&x[c.z]);
    float x3 = __ldg(&x[c.w]);

    // Scatter-add: return value unused -> RED.E.ADD.F32 (no round trip)
    atomicAdd(&out[r.x], v.x * x0);
    atomicAdd(&out[r.y], v.y * x1);
    atomicAdd(&out[r.z], v.z * x2);
    atomicAdd(&out[r.w], v.w * x3);
}

// Tail handler for nnz not divisible by 4 (not expected here, but safe).
__global__ void coo_spmv_tail_kernel(
    const float* __restrict__ x,
    const float* __restrict__ vals,
    const int* __restrict__ rows,
    const int* __restrict__ cols,
    float* __restrict__ out,
    int start, int nnz)
{
    int i = start + blockIdx.x * blockDim.x + threadIdx.x;
    if (i < nnz) {
        atomicAdd(&out[rows[i]], vals[i] * __ldg(&x[cols[i]]));
    }
}

extern "C" void kernel_launch(void* const* d_in, const int* in_sizes, int n_in,
                              void* d_out, int out_size) {
    const float* x    = (const float*)d_in[0];
    const float* vals = (const float*)d_in[1];
    const int*   rows = (const int*)d_in[2];
    const int*   cols = (const int*)d_in[3];
    float* out = (float*)d_out;

    const int nnz = in_sizes[1];

    // Zero-init output (poisoned by harness)
    {
        int n4 = out_size / 4;
        int threads = 256;
        int blocks = (n4 + threads - 1) / threads;
        zero_out_kernel<<<blocks, threads>>>((float4*)out, n4);
        // Handle odd remainder of out_size (out_size = 262144, divisible by 4)
        int rem = out_size - n4 * 4;
        if (rem > 0) {
            coo_spmv_tail_kernel<<<1, 32>>>(x, vals, rows, cols, out, nnz, nnz); // no-op keeper (never needed)
            // (out_size divisible by 4 in this problem; remainder path unused)
        }
    }

    // Main vectorized COO pass
    int nnz4 = nnz / 4;
    if (nnz4 > 0) {
        int threads = 256;
        int blocks = (nnz4 + threads - 1) / threads;
        coo_spmv_kernel<<<blocks, threads>>>(
            x, (const float4*)vals, (const int4*)rows, (const int4*)cols, out, nnz4);
    }

    // Tail (nnz % 4)
    int tail_start = nnz4 * 4;
    int tail = nnz - tail_start;
    if (tail > 0) {
        coo_spmv_tail_kernel<<<1, 256>>>(x, vals, rows, cols, out, tail_start, nnz);
    }
}